// round 13
// baseline (speedup 1.0000x reference)
#include <cuda_runtime.h>

#define TM        8
#define NTHREADS  256
#define M_DIM     8192
#define N_DIM     8192

typedef unsigned long long u64;

// ---- packed f32x2 helpers (sm_103a) ----
__device__ __forceinline__ u64 pack2(float a, float b) {
    u64 r;
    asm("mov.b64 %0, {%1, %2};" : "=l"(r) : "f"(a), "f"(b));
    return r;
}
__device__ __forceinline__ u64 fma2(u64 a, u64 b, u64 c) {
    u64 d;
    asm("fma.rn.f32x2 %0, %1, %2, %3;" : "=l"(d) : "l"(a), "l"(b), "l"(c));
    return d;
}
__device__ __forceinline__ void unpack2(u64 v, float& a, float& b) {
    asm("mov.b64 {%0, %1}, %2;" : "=f"(a), "=f"(b) : "l"(v));
}

// y[r][m] = sum_n code[nib(m,n)] * absmax[(m*N+n)/64] * x[r][n] + bias[m]
// qweight int32 = one packed byte: hi nibble = even col, lo nibble = odd col.
//
// R13 = R2's shape (TM=8 rows, 256 threads: best measured issue rate, x
// amortized over 8 rows) + R6's decode (natural (even,odd) f32x2 pairs:
// x loads are fma2-ready with zero pack movs; one pack2(chi,clo) per byte;
// absmax deferred to one fma2 per row per chunk).
__global__ void __launch_bounds__(NTHREADS, 2)
fp4_gemv_kernel(const float* __restrict__ x,
                const int*   __restrict__ qweight,
                const float* __restrict__ absmax,
                const float* __restrict__ code,
                const float* __restrict__ bias,
                float*       __restrict__ out)
{
    __shared__ float code_sh[16];          // plain 16-entry table (R6: fastest)
    __shared__ float red[8][TM * 4];

    const int tid = threadIdx.x;
    const int w   = tid >> 5;
    const int l   = tid & 31;

    if (tid < 16) code_sh[tid] = code[tid];
    __syncthreads();

    const int m0 = blockIdx.x * TM;
    const int4* __restrict__ qw4 = (const int4*)qweight;

    u64 acc[TM][4];                        // [w-row][x-row] = (even,odd) sums
    #pragma unroll
    for (int mi = 0; mi < TM; ++mi)
        #pragma unroll
        for (int r = 0; r < 4; ++r) acc[mi][r] = 0ULL;

    const int lane_col = w * 32 + l;       // col4 base within each chunk of 256

    #pragma unroll 1
    for (int c = 0; c < 4; ++c) {
        const int col4 = c * 256 + lane_col;   // int4 index in row [0,1024)
        const int n0   = col4 * 8;             // first weight column
        const int amc  = col4 >> 3;            // absmax block within row

        // x pairs: xp[j][r] = (x[r][n0+2j], x[r][n0+2j+1]) — fma2-ready,
        // loaded ONCE per chunk, reused across all 8 W-rows.
        u64 xp[4][4];
        #pragma unroll
        for (int r = 0; r < 4; ++r) {
            ulonglong2 a = __ldg((const ulonglong2*)(x + r * N_DIM + n0));
            ulonglong2 b = __ldg((const ulonglong2*)(x + r * N_DIM + n0 + 4));
            xp[0][r] = a.x; xp[1][r] = a.y;
            xp[2][r] = b.x; xp[3][r] = b.y;
        }

        #pragma unroll
        for (int g = 0; g < 2; ++g) {          // two groups of 4 W-rows
            int4  q[4];
            float am[4];
            #pragma unroll
            for (int mi = 0; mi < 4; ++mi) {
                const int m = m0 + g * 4 + mi;
                q[mi]  = __ldg(&qw4[m * 1024 + col4]);
                am[mi] = __ldg(&absmax[m * 128 + amc]);
            }

            #pragma unroll
            for (int mi = 0; mi < 4; ++mi) {
                const unsigned bb[4] = { (unsigned)q[mi].x, (unsigned)q[mi].y,
                                         (unsigned)q[mi].z, (unsigned)q[mi].w };
                u64 t[4] = {0ULL, 0ULL, 0ULL, 0ULL};   // per x-row, unscaled
                #pragma unroll
                for (int j = 0; j < 4; ++j) {
                    const unsigned b = bb[j];                    // 0..255
                    const u64 c2 = pack2(code_sh[b >> 4], code_sh[b & 15]);
                    t[0] = fma2(c2, xp[j][0], t[0]);
                    t[1] = fma2(c2, xp[j][1], t[1]);
                    t[2] = fma2(c2, xp[j][2], t[2]);
                    t[3] = fma2(c2, xp[j][3], t[3]);
                }
                const u64 am2 = pack2(am[mi], am[mi]);
                const int ai = g * 4 + mi;
                #pragma unroll
                for (int r = 0; r < 4; ++r)
                    acc[ai][r] = fma2(t[r], am2, acc[ai][r]);
            }
        }
    }

    // ---- epilogue: halves sum (free unpack), shfl reduce, cross-warp ----
    float vals[TM * 4];
    #pragma unroll
    for (int mi = 0; mi < TM; ++mi)
        #pragma unroll
        for (int r = 0; r < 4; ++r) {
            float e, o;
            unpack2(acc[mi][r], e, o);
            vals[mi * 4 + r] = e + o;
        }
    #pragma unroll
    for (int i = 0; i < TM * 4; ++i) {
        float v = vals[i];
        v += __shfl_xor_sync(0xffffffffu, v, 16);
        v += __shfl_xor_sync(0xffffffffu, v, 8);
        v += __shfl_xor_sync(0xffffffffu, v, 4);
        v += __shfl_xor_sync(0xffffffffu, v, 2);
        v += __shfl_xor_sync(0xffffffffu, v, 1);
        vals[i] = v;
    }
    if (l == 0) {
        #pragma unroll
        for (int i = 0; i < TM * 4; ++i) red[w][i] = vals[i];
    }
    __syncthreads();

    if (tid < TM * 4) {
        float s = 0.0f;
        #pragma unroll
        for (int ww = 0; ww < 8; ++ww) s += red[ww][tid];
        const int mi = tid >> 2;
        const int r  = tid & 3;
        out[r * M_DIM + m0 + mi] = s + bias[m0 + mi];
    }
}

extern "C" void kernel_launch(void* const* d_in, const int* in_sizes, int n_in,
                              void* d_out, int out_size)
{
    const float* x       = (const float*)d_in[0];
    const int*   qweight = (const int*)  d_in[1];
    const float* absmax  = (const float*)d_in[2];
    const float* code    = (const float*)d_in[3];
    const float* bias    = (const float*)d_in[4];
    float*       out     = (float*)d_out;

    fp4_gemv_kernel<<<M_DIM / TM, NTHREADS>>>(x, qweight, absmax, code, bias, out);
}

// round 14
// speedup vs baseline: 1.1047x; 1.1047x over previous
#include <cuda_runtime.h>

#define TM        4
#define NTHREADS  128
#define M_DIM     8192
#define N_DIM     8192

typedef unsigned long long u64;

// ---- packed f32x2 helpers (sm_103a) ----
__device__ __forceinline__ u64 pack2(float a, float b) {
    u64 r;
    asm("mov.b64 %0, {%1, %2};" : "=l"(r) : "f"(a), "f"(b));
    return r;
}
__device__ __forceinline__ u64 fma2(u64 a, u64 b, u64 c) {
    u64 d;
    asm("fma.rn.f32x2 %0, %1, %2, %3;" : "=l"(d) : "l"(a), "l"(b), "l"(c));
    return d;
}
__device__ __forceinline__ void unpack2(u64 v, float& a, float& b) {
    asm("mov.b64 {%0, %1}, %2;" : "=f"(a), "=f"(b) : "l"(v));
}

// y[r][m] = sum_n code[nib(m,n)] * absmax[(m*N+n)/64] * x[r][n] + bias[m]
// qweight int32 = one packed byte: hi nibble = even col, lo nibble = odd col.
//
// R6 structure (best: 41.7us) with ONE change: a 256-entry precomputed pair
// table code2[b] = (code[hi], code[lo]) in smem. Decode per byte is a single
// LDS.64 instead of 2x LDS.32 + 2x LOP3 + pack2 -> ~20% fewer issue slots at
// identical L1 wavefront count.
__global__ void __launch_bounds__(NTHREADS, 4)
fp4_gemv_kernel(const float* __restrict__ x,
                const int*   __restrict__ qweight,
                const float* __restrict__ absmax,
                const float* __restrict__ code,
                const float* __restrict__ bias,
                float*       __restrict__ out)
{
    __shared__ u64   code2_sh[256];        // [byte] -> (code[hi], code[lo])
    __shared__ float red[4][TM * 4];

    const int tid = threadIdx.x;
    const int w   = tid >> 5;
    const int l   = tid & 31;

    #pragma unroll
    for (int i = tid; i < 256; i += NTHREADS)
        code2_sh[i] = pack2(code[i >> 4], code[i & 15]);
    __syncthreads();

    const int m0 = blockIdx.x * TM;
    const int4* __restrict__ qw4 = (const int4*)qweight;

    u64 acc[TM][4];                        // [w-row][x-row] = (even,odd) sums
    #pragma unroll
    for (int mi = 0; mi < TM; ++mi)
        #pragma unroll
        for (int r = 0; r < 4; ++r) acc[mi][r] = 0ULL;

    const int lane_col = w * 32 + l;       // col4 base within each chunk of 128

    #pragma unroll 2
    for (int c = 0; c < 8; ++c) {
        const int col4 = c * 128 + lane_col;   // int4 index in row [0,1024)
        const int n0   = col4 * 8;             // first weight column

        // ---- batch all global loads up front (max MLP) ----
        int4  q[TM];
        float am[TM];
        #pragma unroll
        for (int mi = 0; mi < TM; ++mi) {
            q[mi]  = __ldcs(&qw4[(m0 + mi) * 1024 + col4]);       // streaming
            am[mi] = __ldcs(&absmax[(m0 + mi) * 128 + (col4 >> 3)]);
        }

        // x pairs: xp[j][r] = (x[r][n0+2j], x[r][n0+2j+1]) — fma2-ready
        u64 xp[4][4];
        #pragma unroll
        for (int r = 0; r < 4; ++r) {
            ulonglong2 a = __ldg((const ulonglong2*)(x + r * N_DIM + n0));
            ulonglong2 b = __ldg((const ulonglong2*)(x + r * N_DIM + n0 + 4));
            xp[0][r] = a.x; xp[1][r] = a.y;
            xp[2][r] = b.x; xp[3][r] = b.y;
        }

        // ---- decode (single LDS.64 per byte) + accumulate ----
        #pragma unroll
        for (int mi = 0; mi < TM; ++mi) {
            const unsigned bb[4] = { (unsigned)q[mi].x, (unsigned)q[mi].y,
                                     (unsigned)q[mi].z, (unsigned)q[mi].w };
            u64 t[4] = {0ULL, 0ULL, 0ULL, 0ULL};   // per x-row, unscaled
            #pragma unroll
            for (int j = 0; j < 4; ++j) {
                const u64 c2 = code2_sh[bb[j]];            // one LDS.64
                t[0] = fma2(c2, xp[j][0], t[0]);
                t[1] = fma2(c2, xp[j][1], t[1]);
                t[2] = fma2(c2, xp[j][2], t[2]);
                t[3] = fma2(c2, xp[j][3], t[3]);
            }
            const u64 am2 = pack2(am[mi], am[mi]);
            #pragma unroll
            for (int r = 0; r < 4; ++r)
                acc[mi][r] = fma2(t[r], am2, acc[mi][r]);
        }
    }

    // ---- epilogue: halves sum (free unpack), shfl reduce, cross-warp ----
    float vals[TM * 4];
    #pragma unroll
    for (int mi = 0; mi < TM; ++mi)
        #pragma unroll
        for (int r = 0; r < 4; ++r) {
            float e, o;
            unpack2(acc[mi][r], e, o);
            vals[mi * 4 + r] = e + o;
        }
    #pragma unroll
    for (int i = 0; i < TM * 4; ++i) {
        float v = vals[i];
        v += __shfl_xor_sync(0xffffffffu, v, 16);
        v += __shfl_xor_sync(0xffffffffu, v, 8);
        v += __shfl_xor_sync(0xffffffffu, v, 4);
        v += __shfl_xor_sync(0xffffffffu, v, 2);
        v += __shfl_xor_sync(0xffffffffu, v, 1);
        vals[i] = v;
    }
    if (l == 0) {
        #pragma unroll
        for (int i = 0; i < TM * 4; ++i) red[w][i] = vals[i];
    }
    __syncthreads();

    if (tid < TM * 4) {
        float s = red[0][tid] + red[1][tid] + red[2][tid] + red[3][tid];
        const int mi = tid >> 2;
        const int r  = tid & 3;
        out[r * M_DIM + m0 + mi] = s + bias[m0 + mi];
    }
}

extern "C" void kernel_launch(void* const* d_in, const int* in_sizes, int n_in,
                              void* d_out, int out_size)
{
    const float* x       = (const float*)d_in[0];
    const int*   qweight = (const int*)  d_in[1];
    const float* absmax  = (const float*)d_in[2];
    const float* code    = (const float*)d_in[3];
    const float* bias    = (const float*)d_in[4];
    float*       out     = (float*)d_out;

    fp4_gemv_kernel<<<M_DIM / TM, NTHREADS>>>(x, qweight, absmax, code, bias, out);
}

// round 15
// speedup vs baseline: 1.3835x; 1.2523x over previous
#include <cuda_runtime.h>

#define TM        4
#define NTHREADS  128
#define M_DIM     8192
#define N_DIM     8192

typedef unsigned long long u64;

// ---- packed f32x2 helpers (sm_103a) ----
__device__ __forceinline__ u64 pack2(float a, float b) {
    u64 r;
    asm("mov.b64 %0, {%1, %2};" : "=l"(r) : "f"(a), "f"(b));
    return r;
}
__device__ __forceinline__ u64 fma2(u64 a, u64 b, u64 c) {
    u64 d;
    asm("fma.rn.f32x2 %0, %1, %2, %3;" : "=l"(d) : "l"(a), "l"(b), "l"(c));
    return d;
}
__device__ __forceinline__ void unpack2(u64 v, float& a, float& b) {
    asm("mov.b64 {%0, %1}, %2;" : "=f"(a), "=f"(b) : "l"(v));
}

// y[r][m] = sum_n code[nib(m,n)] * absmax[(m*N+n)/64] * x[r][n] + bias[m]
// qweight int32 = one packed byte: hi nibble = even col, lo nibble = odd col.
//
// EXACTLY R6's structure/decode (best known: 41.7us), with one change:
// xp is held as 2-column-pair halves (16 regs instead of 32) processed
// sequentially, cutting the live register set so __launch_bounds__(128,5)
// gives 20 warps/SM instead of 16 — same slots, same wavefronts.
__global__ void __launch_bounds__(NTHREADS, 5)
fp4_gemv_kernel(const float* __restrict__ x,
                const int*   __restrict__ qweight,
                const float* __restrict__ absmax,
                const float* __restrict__ code,
                const float* __restrict__ bias,
                float*       __restrict__ out)
{
    __shared__ float code_sh[16];          // R6 nibble table (proven best decode)
    __shared__ float red[4][TM * 4];

    const int tid = threadIdx.x;
    const int w   = tid >> 5;
    const int l   = tid & 31;

    if (tid < 16) code_sh[tid] = code[tid];
    __syncthreads();

    const int m0 = blockIdx.x * TM;
    const int4* __restrict__ qw4 = (const int4*)qweight;

    u64 acc[TM][4];                        // [w-row][x-row] = (even,odd) sums
    #pragma unroll
    for (int mi = 0; mi < TM; ++mi)
        #pragma unroll
        for (int r = 0; r < 4; ++r) acc[mi][r] = 0ULL;

    const int lane_col = w * 32 + l;       // col4 base within each chunk of 128

    #pragma unroll 2
    for (int c = 0; c < 8; ++c) {
        const int col4 = c * 128 + lane_col;   // int4 index in row [0,1024)
        const int n0   = col4 * 8;             // first weight column

        // q + absmax batched up front (max MLP), exactly as R6
        int4  q[TM];
        float am[TM];
        #pragma unroll
        for (int mi = 0; mi < TM; ++mi) {
            q[mi]  = __ldg(&qw4[(m0 + mi) * 1024 + col4]);
            am[mi] = __ldg(&absmax[(m0 + mi) * 128 + (col4 >> 3)]);
        }

        // Two halves of 4 columns each: xp footprint 16 regs instead of 32.
        #pragma unroll
        for (int h = 0; h < 2; ++h) {
            const int nh = n0 + h * 4;
            u64 xp[2][4];                  // xp[j][r] = (x[r][nh+2j], x[r][nh+2j+1])
            #pragma unroll
            for (int r = 0; r < 4; ++r) {
                ulonglong2 a = __ldg((const ulonglong2*)(x + r * N_DIM + nh));
                xp[0][r] = a.x; xp[1][r] = a.y;
            }

            #pragma unroll
            for (int mi = 0; mi < TM; ++mi) {
                const unsigned b0 =
                    (unsigned)(h == 0 ? q[mi].x : q[mi].z);   // cols nh, nh+1
                const unsigned b1 =
                    (unsigned)(h == 0 ? q[mi].y : q[mi].w);   // cols nh+2, nh+3
                u64 t[4] = {0ULL, 0ULL, 0ULL, 0ULL};
                {
                    const u64 c2 = pack2(code_sh[b0 >> 4], code_sh[b0 & 15]);
                    t[0] = fma2(c2, xp[0][0], t[0]);
                    t[1] = fma2(c2, xp[0][1], t[1]);
                    t[2] = fma2(c2, xp[0][2], t[2]);
                    t[3] = fma2(c2, xp[0][3], t[3]);
                }
                {
                    const u64 c2 = pack2(code_sh[b1 >> 4], code_sh[b1 & 15]);
                    t[0] = fma2(c2, xp[1][0], t[0]);
                    t[1] = fma2(c2, xp[1][1], t[1]);
                    t[2] = fma2(c2, xp[1][2], t[2]);
                    t[3] = fma2(c2, xp[1][3], t[3]);
                }
                const u64 am2 = pack2(am[mi], am[mi]);
                #pragma unroll
                for (int r = 0; r < 4; ++r)
                    acc[mi][r] = fma2(t[r], am2, acc[mi][r]);
            }
        }
    }

    // ---- epilogue: halves sum (free unpack), shfl reduce, cross-warp ----
    float vals[TM * 4];
    #pragma unroll
    for (int mi = 0; mi < TM; ++mi)
        #pragma unroll
        for (int r = 0; r < 4; ++r) {
            float e, o;
            unpack2(acc[mi][r], e, o);
            vals[mi * 4 + r] = e + o;
        }
    #pragma unroll
    for (int i = 0; i < TM * 4; ++i) {
        float v = vals[i];
        v += __shfl_xor_sync(0xffffffffu, v, 16);
        v += __shfl_xor_sync(0xffffffffu, v, 8);
        v += __shfl_xor_sync(0xffffffffu, v, 4);
        v += __shfl_xor_sync(0xffffffffu, v, 2);
        v += __shfl_xor_sync(0xffffffffu, v, 1);
        vals[i] = v;
    }
    if (l == 0) {
        #pragma unroll
        for (int i = 0; i < TM * 4; ++i) red[w][i] = vals[i];
    }
    __syncthreads();

    if (tid < TM * 4) {
        float s = red[0][tid] + red[1][tid] + red[2][tid] + red[3][tid];
        const int mi = tid >> 2;
        const int r  = tid & 3;
        out[r * M_DIM + m0 + mi] = s + bias[m0 + mi];
    }
}

extern "C" void kernel_launch(void* const* d_in, const int* in_sizes, int n_in,
                              void* d_out, int out_size)
{
    const float* x       = (const float*)d_in[0];
    const int*   qweight = (const int*)  d_in[1];
    const float* absmax  = (const float*)d_in[2];
    const float* code    = (const float*)d_in[3];
    const float* bias    = (const float*)d_in[4];
    float*       out     = (float*)d_out;

    fp4_gemv_kernel<<<M_DIM / TM, NTHREADS>>>(x, qweight, absmax, code, bias, out);
}